// round 17
// baseline (speedup 1.0000x reference)
#include <cuda_runtime.h>
#include <cuda_fp16.h>
#include <cstdint>
#include <cstddef>

// ---------------- problem constants ----------------
#define NBATCH 2
#define LSEQ   2048
#define DIM    1024
#define NH     16
#define DH     64
#define CHK    128
#define NCHK   (LSEQ / CHK)      // 16
#define MROWS  (NBATCH * LSEQ)   // 4096

// ---------------- device scratch (no allocs allowed) ----------------
__device__ __align__(16) __half g_Xh[2][MROWS * DIM];    // fp16 inputs (q,k)
__device__ __align__(16) __half g_Wh[3][DIM * DIM];      // fp16 weights
__device__ __align__(16) __half g_Oh[3][MROWS * DIM];    // fp16 projected Q,K,V
__device__ __align__(16) __half g_Sh[NBATCH * NH * NCHK * DH * DH];  // excl prefix fp16

// ---------------- small helpers ----------------
__device__ __forceinline__ uint32_t smem_u32(const void* p) {
    uint32_t a;
    asm("{ .reg .u64 t; cvta.to.shared.u64 t, %1; cvt.u32.u64 %0, t; }" : "=r"(a) : "l"(p));
    return a;
}
__device__ __forceinline__ void cp16(uint32_t s, const void* g) {
    asm volatile("cp.async.cg.shared.global [%0], [%1], 16;" :: "r"(s), "l"(g));
}
#define CP_COMMIT() asm volatile("cp.async.commit_group;" ::: "memory")
#define CP_WAIT1()  asm volatile("cp.async.wait_group 1;" ::: "memory")
#define CP_WAIT0()  asm volatile("cp.async.wait_group 0;" ::: "memory")

__device__ __forceinline__ void mma16816h(float* c, const uint32_t* a, const uint32_t* b) {
    asm volatile(
        "mma.sync.aligned.m16n8k16.row.col.f32.f16.f16.f32 "
        "{%0,%1,%2,%3}, {%4,%5,%6,%7}, {%8,%9}, {%0,%1,%2,%3};"
        : "+f"(c[0]), "+f"(c[1]), "+f"(c[2]), "+f"(c[3])
        : "r"(a[0]), "r"(a[1]), "r"(a[2]), "r"(a[3]), "r"(b[0]), "r"(b[1]));
}
__device__ __forceinline__ void ldsm4(uint32_t* r, uint32_t addr) {
    asm volatile("ldmatrix.sync.aligned.m8n8.x4.shared.b16 {%0,%1,%2,%3}, [%4];"
                 : "=r"(r[0]), "=r"(r[1]), "=r"(r[2]), "=r"(r[3]) : "r"(addr));
}
__device__ __forceinline__ void ldsm4t(uint32_t* r, uint32_t addr) {
    asm volatile("ldmatrix.sync.aligned.m8n8.x4.trans.shared.b16 {%0,%1,%2,%3}, [%4];"
                 : "=r"(r[0]), "=r"(r[1]), "=r"(r[2]), "=r"(r[3]) : "r"(addr));
}

// swizzled byte offset: 128B-pitch rows, 16B chunk c (0..7)
__device__ __forceinline__ uint32_t swz(int row, int c) {
    return (uint32_t)(row * 128 + ((c ^ (row & 7)) << 4));
}
// 256B-pitch rows, 16 chunks: XOR low 3 bits only
__device__ __forceinline__ uint32_t swzA(int row, int c) {
    return (uint32_t)(row * 256 + (((c & 8) | ((c & 7) ^ (row & 7))) << 4));
}

// ---------------- fp16 conversion (2x unrolled, batched loads) ----------------
__global__ __launch_bounds__(256)
void conv_split(const float* __restrict__ q, const float* __restrict__ k,
                const float* __restrict__ wq, const float* __restrict__ wk,
                const float* __restrict__ wv)
{
    int y = blockIdx.y;
    const float* src;
    __half* dst;
    int n;
    switch (y) {
        case 0: src = q;  dst = g_Xh[0]; n = MROWS * DIM; break;
        case 1: src = k;  dst = g_Xh[1]; n = MROWS * DIM; break;
        case 2: src = wq; dst = g_Wh[0]; n = DIM * DIM;   break;
        case 3: src = wk; dst = g_Wh[1]; n = DIM * DIM;   break;
        default: src = wv; dst = g_Wh[2]; n = DIM * DIM;  break;
    }
    const int n4 = n >> 2;
    const int stride = gridDim.x * blockDim.x;
    for (int i = blockIdx.x * blockDim.x + threadIdx.x; i < n4; i += 2 * stride) {
        const int i1 = i + stride;
        float4 f0 = ((const float4*)src)[i];
        float4 f1;
        const bool ok = (i1 < n4);
        if (ok) f1 = ((const float4*)src)[i1];
        ushort4 u0 = make_ushort4(
            __half_as_ushort(__float2half(f0.x)), __half_as_ushort(__float2half(f0.y)),
            __half_as_ushort(__float2half(f0.z)), __half_as_ushort(__float2half(f0.w)));
        ((ushort4*)dst)[i] = u0;
        if (ok) {
            ushort4 u1 = make_ushort4(
                __half_as_ushort(__float2half(f1.x)), __half_as_ushort(__float2half(f1.y)),
                __half_as_ushort(__float2half(f1.z)), __half_as_ushort(__float2half(f1.w)));
            ((ushort4*)dst)[i1] = u1;
        }
    }
}

// ---------------- HMMA projection GEMM (+ fused intra-warp softmax) ----------------
#define STAGE_BYTES 32768
#define SMEM_TOTAL  (3 * STAGE_BYTES)

__global__ __launch_bounds__(256, 2)
void proj_hmma()
{
    extern __shared__ char smem[];
    const uint32_t sb = smem_u32(smem);

    const int tid = threadIdx.x;
    const int wid = tid >> 5;
    const int lane = tid & 31;
    const int wm = wid >> 1;       // 0..3 (32-row block)
    const int wn = wid & 1;        // 0..1 (64-col block = head segment)
    const int z = blockIdx.z;

    const __half* __restrict__ A = g_Xh[z ? 1 : 0];
    const __half* __restrict__ B = g_Wh[z];
    __half* __restrict__ Out = g_Oh[z];

    const int m0 = blockIdx.y * 128;
    const int n0 = blockIdx.x * 128;

    float acc[2][8][4];
#pragma unroll
    for (int i = 0; i < 2; i++)
#pragma unroll
        for (int j = 0; j < 8; j++)
#pragma unroll
            for (int r = 0; r < 4; r++) acc[i][j][r] = 0.f;

    const int lrow = tid >> 1;
    const int lc4  = (tid & 1) * 4;
    auto load_tile = [&](int kk, int stg) {
        const int k0 = kk * 64;
        const uint32_t sa = sb + stg * STAGE_BYTES;
        const uint32_t sbB = sa + 16384;
        const __half* ga = A + (size_t)(m0 + lrow) * DIM + k0 + lc4 * 8;
        const __half* gb = B + (size_t)(n0 + lrow) * DIM + k0 + lc4 * 8;
#pragma unroll
        for (int c = 0; c < 4; c++) {
            cp16(sa  + swz(lrow, lc4 + c), ga + c * 8);
            cp16(sbB + swz(lrow, lc4 + c), gb + c * 8);
        }
    };

    const int a_row = (lane & 7) + ((lane >> 3) & 1) * 8;
    const int a_cofs = lane >> 4;
    const int b_row0 = ((lane >> 4) & 1) * 8 + (lane & 7);
    const int b_cofs = (lane >> 3) & 1;

    load_tile(0, 0); CP_COMMIT();
    load_tile(1, 1); CP_COMMIT();

    for (int kk = 0; kk < 16; kk++) {
        const int stg = kk % 3;
        CP_WAIT1();
        __syncthreads();
        if (kk + 2 < 16) { load_tile(kk + 2, (kk + 2) % 3); CP_COMMIT(); }

        const uint32_t sa = sb + stg * STAGE_BYTES;
        const uint32_t sbB = sa + 16384;

#pragma unroll
        for (int ks = 0; ks < 4; ks++) {
            const int c0 = ks * 2;
            uint32_t a[2][4], b[16];
#pragma unroll
            for (int i = 0; i < 2; i++)
                ldsm4(a[i], sa + swz(wm * 32 + i * 16 + a_row, c0 + a_cofs));
#pragma unroll
            for (int jp = 0; jp < 4; jp++)
                ldsm4(&b[jp * 4], sbB + swz(wn * 64 + jp * 16 + b_row0, c0 + b_cofs));
#pragma unroll
            for (int i = 0; i < 2; i++)
#pragma unroll
                for (int j = 0; j < 8; j++)
                    mma16816h(acc[i][j], a[i], &b[j * 2]);
        }
    }

    const int g = lane >> 2;
    const int tg = lane & 3;

    if (z < 2) {
#pragma unroll
        for (int i = 0; i < 2; i++)
#pragma unroll
            for (int h = 0; h < 2; h++) {
                float m = acc[i][0][h * 2];
#pragma unroll
                for (int j = 0; j < 8; j++) {
                    m = fmaxf(m, acc[i][j][h * 2]);
                    m = fmaxf(m, acc[i][j][h * 2 + 1]);
                }
                m = fmaxf(m, __shfl_xor_sync(0xffffffffu, m, 1));
                m = fmaxf(m, __shfl_xor_sync(0xffffffffu, m, 2));
                float s = 0.f;
#pragma unroll
                for (int j = 0; j < 8; j++) {
                    float e0 = __expf(acc[i][j][h * 2]     - m);
                    float e1 = __expf(acc[i][j][h * 2 + 1] - m);
                    acc[i][j][h * 2] = e0; acc[i][j][h * 2 + 1] = e1;
                    s += e0 + e1;
                }
                s += __shfl_xor_sync(0xffffffffu, s, 1);
                s += __shfl_xor_sync(0xffffffffu, s, 2);
                float inv = 1.0f / s;
#pragma unroll
                for (int j = 0; j < 8; j++) {
                    acc[i][j][h * 2]     *= inv;
                    acc[i][j][h * 2 + 1] *= inv;
                }
            }
    }

#pragma unroll
    for (int i = 0; i < 2; i++) {
        const int r0 = m0 + wm * 32 + i * 16 + g;
#pragma unroll
        for (int j = 0; j < 8; j++) {
            const int cc = n0 + wn * 64 + j * 8 + tg * 2;
            *(__half2*)&Out[(size_t)r0 * DIM + cc] =
                __floats2half2_rn(acc[i][j][0], acc[i][j][1]);
            *(__half2*)&Out[(size_t)(r0 + 8) * DIM + cc] =
                __floats2half2_rn(acc[i][j][2], acc[i][j][3]);
        }
    }
}

// ---------------- fused chunk-KV + exclusive prefix scan ----------------
// One block per (n,h). Walks 16 chunks with a 2-stage cp.async double buffer;
// the running prefix lives in the fp32 MMA accumulator (mma accumulate = scan).
// Stores S_excl (fp16) BEFORE accumulating each chunk's P.
#define CS_STAGE 32768
#define CS_BYTES (2 * CS_STAGE)   // 64 KB

__global__ __launch_bounds__(256)
void chunk_scan()
{
    extern __shared__ char smem[];
    const uint32_t sb = smem_u32(smem);

    const int nh = blockIdx.x;
    const int n = nh >> 4, h = nh & 15;
    const int tid = threadIdx.x;
    const int lane = tid & 31;
    const int wid = tid >> 5;

    const int lrow = tid >> 1, lc4 = (tid & 1) * 4;
    auto load_chunk = [&](int c, int stg) {
        const size_t base = ((size_t)(n * LSEQ + c * CHK)) * DIM + h * DH;
        const __half* gk = g_Oh[1] + base + (size_t)lrow * DIM;
        const __half* gv = g_Oh[2] + base + (size_t)lrow * DIM;
        const uint32_t s0 = sb + stg * CS_STAGE;
#pragma unroll
        for (int c4 = 0; c4 < 4; c4++) {
            cp16(s0 + swz(lrow, lc4 + c4), gk + (lc4 + c4) * 8);
            cp16(s0 + 16384 + swz(lrow, lc4 + c4), gv + (lc4 + c4) * 8);
        }
    };

    const int wmc = wid >> 1;    // d1 block (m16)
    const int wnc = wid & 1;     // d2 block (n32)
    const int ta_krow = ((lane >> 4) << 3) + (lane & 7);
    const int ta_mch  = (lane >> 3) & 1;
    const int tb_krow = (((lane >> 3) & 1) << 3) + (lane & 7);
    const int tb_nch  = lane >> 4;
    const int g = lane >> 2, tg = lane & 3;

    float Sacc[4][4];
#pragma unroll
    for (int j = 0; j < 4; j++)
#pragma unroll
        for (int r = 0; r < 4; r++) Sacc[j][r] = 0.f;

    load_chunk(0, 0); CP_COMMIT();

    __half* Sg = g_Sh + (size_t)nh * NCHK * (DH * DH);

    for (int c = 0; c < NCHK; c++) {
        const int stg = c & 1;
        CP_WAIT0();
        __syncthreads();
        if (c + 1 < NCHK) { load_chunk(c + 1, stg ^ 1); CP_COMMIT(); }

        // store exclusive prefix for this chunk
        __half* Sc = Sg + c * (DH * DH);
#pragma unroll
        for (int j = 0; j < 4; j++) {
            int row = 16 * wmc + g;
            int col = 32 * wnc + 8 * j + 2 * tg;
            *(__half2*)&Sc[row * 64 + col] = __floats2half2_rn(Sacc[j][0], Sacc[j][1]);
            *(__half2*)&Sc[(row + 8) * 64 + col] = __floats2half2_rn(Sacc[j][2], Sacc[j][3]);
        }

        // accumulate this chunk's P = k^T v into the running sum
        const uint32_t s0 = sb + stg * CS_STAGE;
#pragma unroll
        for (int kt = 0; kt < 8; kt++) {
            const int t0 = kt * 16;
            uint32_t a[4], b[8];
            ldsm4t(a, s0 + swz(t0 + ta_krow, 2 * wmc + ta_mch));
#pragma unroll
            for (int jp = 0; jp < 2; jp++)
                ldsm4t(&b[jp * 4], s0 + 16384 + swz(t0 + tb_krow, 4 * wnc + 2 * jp + tb_nch));
#pragma unroll
            for (int j = 0; j < 4; j++)
                mma16816h(Sacc[j], a, &b[j * 2]);
        }
        __syncthreads();
    }
}

// ---------------- attention output on HMMA ----------------
#define AT_QH 0
#define AT_KH 16384
#define AT_VH 32768
#define AT_SH 49152
#define AT_AH 57344
#define AT_BYTES (AT_AH + 32768)   // 90112

__global__ __launch_bounds__(256, 2)
void attn_out(float* __restrict__ out)
{
    extern __shared__ char smem[];
    const uint32_t sb = smem_u32(smem);

    const int c = blockIdx.x;
    const int nh = blockIdx.y;
    const int n = nh >> 4, h = nh & 15;
    const size_t base = ((size_t)(n * LSEQ + c * CHK)) * DIM + h * DH;
    const int tid = threadIdx.x;
    const int lane = tid & 31;
    const int wid = tid >> 5;
    const int g = lane >> 2, tg = lane & 3;

    const int a_row = (lane & 7) + ((lane >> 3) & 1) * 8;
    const int a_cofs = lane >> 4;
    const int b_row0 = ((lane >> 4) & 1) * 8 + (lane & 7);
    const int b_cofs = (lane >> 3) & 1;
    const int tb_krow = (((lane >> 3) & 1) << 3) + (lane & 7);
    const int tb_nch  = lane >> 4;

    {
        int lrow = tid >> 1, lc4 = (tid & 1) * 4;
        const __half* gq = g_Oh[0] + base + (size_t)lrow * DIM;
        const __half* gk = g_Oh[1] + base + (size_t)lrow * DIM;
        const __half* gv = g_Oh[2] + base + (size_t)lrow * DIM;
#pragma unroll
        for (int c4 = 0; c4 < 4; c4++) {
            int ch = lc4 + c4;
            cp16(sb + AT_QH + swz(lrow, ch), gq + ch * 8);
            cp16(sb + AT_KH + swz(lrow, ch), gk + ch * 8);
            cp16(sb + AT_VH + swz(lrow, ch), gv + ch * 8);
        }
        if (c > 0 && tid < 128) {
            const __half* gs = g_Sh + ((size_t)nh * NCHK + c) * (DH * DH) + lrow * 64;
#pragma unroll
            for (int c4 = 0; c4 < 4; c4++) {
                int ch = lc4 + c4;
                cp16(sb + AT_SH + swz(lrow, ch), gs + ch * 8);
            }
        }
    }
    CP_COMMIT(); CP_WAIT0(); __syncthreads();

    // stage 1: A = causal(q k^T) -> AH fp16
    {
        const int wm1 = wid >> 2, wn1 = wid & 3;
        if (wm1 == 0 && wn1 >= 2) {
            int row = (wn1 - 2) * 32 + lane;
            uint4 zz = make_uint4(0, 0, 0, 0);
#pragma unroll
            for (int cc8 = 0; cc8 < 8; cc8++)
                *(uint4*)(smem + AT_AH + row * 256 + 128 + cc8 * 16) = zz;
        } else {
            float acc1[4][4][4];
#pragma unroll
            for (int i = 0; i < 4; i++)
#pragma unroll
                for (int j = 0; j < 4; j++)
#pragma unroll
                    for (int r = 0; r < 4; r++) acc1[i][j][r] = 0.f;

#pragma unroll
            for (int ks = 0; ks < 4; ks++) {
                const int c0 = ks * 2;
                uint32_t a[4][4], b[8];
#pragma unroll
                for (int i = 0; i < 4; i++)
                    ldsm4(a[i], sb + AT_QH + swz(64 * wm1 + 16 * i + a_row, c0 + a_cofs));
#pragma unroll
                for (int jp = 0; jp < 2; jp++)
                    ldsm4(&b[jp * 4], sb + AT_KH + swz(32 * wn1 + 16 * jp + b_row0, c0 + b_cofs));
#pragma unroll
                for (int i = 0; i < 4; i++)
#pragma unroll
                    for (int j = 0; j < 4; j++)
                        mma16816h(acc1[i][j], a[i], &b[j * 2]);
            }
#pragma unroll
            for (int i = 0; i < 4; i++) {
                int r0 = 64 * wm1 + 16 * i + g;
#pragma unroll
                for (int j = 0; j < 4; j++) {
                    int cb = 32 * wn1 + 8 * j + 2 * tg;
                    int ch = cb >> 3;
                    float v0 = (cb     <= r0) ? acc1[i][j][0] : 0.f;
                    float v1 = (cb + 1 <= r0) ? acc1[i][j][1] : 0.f;
                    *(__half2*)(smem + AT_AH + swzA(r0, ch) + (cb & 7) * 2) =
                        __floats2half2_rn(v0, v1);
                    int r1 = r0 + 8;
                    float v2 = (cb     <= r1) ? acc1[i][j][2] : 0.f;
                    float v3 = (cb + 1 <= r1) ? acc1[i][j][3] : 0.f;
                    *(__half2*)(smem + AT_AH + swzA(r1, ch) + (cb & 7) * 2) =
                        __floats2half2_rn(v2, v3);
                }
            }
        }
    }
    __syncthreads();

    // stage 2: o = q @ S_excl + A @ v
    const int wm2 = wid >> 1;
    const int wn2 = wid & 1;
    float o2[2][4][4];
#pragma unroll
    for (int i = 0; i < 2; i++)
#pragma unroll
        for (int j = 0; j < 4; j++)
#pragma unroll
            for (int r = 0; r < 4; r++) o2[i][j][r] = 0.f;

    if (c > 0) {
#pragma unroll
        for (int ks = 0; ks < 4; ks++) {
            const int c0 = ks * 2, d0 = ks * 16;
            uint32_t a[2][4], b[8];
#pragma unroll
            for (int i = 0; i < 2; i++)
                ldsm4(a[i], sb + AT_QH + swz(32 * wm2 + 16 * i + a_row, c0 + a_cofs));
#pragma unroll
            for (int jp = 0; jp < 2; jp++)
                ldsm4t(&b[jp * 4], sb + AT_SH + swz(d0 + tb_krow, 4 * wn2 + 2 * jp + tb_nch));
#pragma unroll
            for (int i = 0; i < 2; i++)
#pragma unroll
                for (int j = 0; j < 4; j++)
                    mma16816h(o2[i][j], a[i], &b[j * 2]);
        }
    }
    const int nkt = 2 * (wm2 + 1);
    for (int kt = 0; kt < nkt; kt++) {
        const int s0 = kt * 16;
        uint32_t a[2][4], b[8];
#pragma unroll
        for (int i = 0; i < 2; i++)
            ldsm4(a[i], sb + AT_AH + swzA(32 * wm2 + 16 * i + a_row, 2 * kt + a_cofs));
#pragma unroll
        for (int jp = 0; jp < 2; jp++)
            ldsm4t(&b[jp * 4], sb + AT_VH + swz(s0 + tb_krow, 4 * wn2 + 2 * jp + tb_nch));
#pragma unroll
        for (int i = 0; i < 2; i++)
#pragma unroll
            for (int j = 0; j < 4; j++)
                mma16816h(o2[i][j], a[i], &b[j * 2]);
    }

#pragma unroll
    for (int i = 0; i < 2; i++) {
        int row = 32 * wm2 + 16 * i + g;
#pragma unroll
        for (int j = 0; j < 4; j++) {
            int col = 32 * wn2 + 8 * j + 2 * tg;
            *(float2*)&out[base + (size_t)row * DIM + col] =
                make_float2(o2[i][j][0], o2[i][j][1]);
            *(float2*)&out[base + (size_t)(row + 8) * DIM + col] =
                make_float2(o2[i][j][2], o2[i][j][3]);
        }
    }
}

// ---------------------------------------------------------------------------
extern "C" void kernel_launch(void* const* d_in, const int* in_sizes, int n_in,
                              void* d_out, int out_size)
{
    const float* query = (const float*)d_in[0];
    const float* key   = (const float*)d_in[1];
    const float* Wq    = (const float*)d_in[2];
    const float* Wk    = (const float*)d_in[3];
    const float* Wv    = (const float*)d_in[4];
    float* out = (float*)d_out;

    cudaFuncSetAttribute(proj_hmma, cudaFuncAttributeMaxDynamicSharedMemorySize, SMEM_TOTAL);
    cudaFuncSetAttribute(chunk_scan, cudaFuncAttributeMaxDynamicSharedMemorySize, CS_BYTES);
    cudaFuncSetAttribute(attn_out, cudaFuncAttributeMaxDynamicSharedMemorySize, AT_BYTES);

    // 1. fp16 conversion
    conv_split<<<dim3(384, 5), 256>>>(query, key, Wq, Wk, Wv);

    // 2. projections (fp16 HMMA, fused intra-warp softmax, fp16 output)
    proj_hmma<<<dim3(8, 32, 3), 256, SMEM_TOTAL>>>();

    // 3. fused chunk-KV sums + exclusive prefix (running sum in MMA accum)
    chunk_scan<<<NBATCH * NH, 256, CS_BYTES>>>();

    // 4. attention output
    dim3 agrid(NCHK, NBATCH * NH);
    attn_out<<<agrid, 256, AT_BYTES>>>(out);
}